// round 5
// baseline (speedup 1.0000x reference)
#include <cuda_runtime.h>

// GemorestructNet: variable-radius box-blur composite via mean-centered SAT,
// smem-tiled gather with precomputed corner-offset table + interior fast path.

#define RADIUS 25
#define KMAX 28
#define TABLE 57
#define IMG_H 512
#define IMG_W 512
#define NIMG 24          // B*C
#define SW 512           // SAT stride
#define NCHUNK 8
#define CROWS 64         // 512 / NCHUNK

// gather tiling
#define TX 64
#define TY 16
#define HALO 29                   // KMAX+1
#define SMW (TX + 2*KMAX + 1)     // 121
#define SMH (TY + 2*KMAX + 1)     // 73

__device__ float g_sat [NIMG * SW * SW];
__device__ float g_csum[NIMG * NCHUNK * SW];

// k(i) = i + floor((i+5)/7)
__device__ __forceinline__ int k_of(int i) { return i + (i + 5) / 7; }

// ---------------------------------------------------------------------------
// Kernel A: per-row inclusive prefix sum of (x - 0.5).
// ---------------------------------------------------------------------------
__global__ void row_scan_kernel(const float* __restrict__ x) {
    const int t    = threadIdx.x;            // 0..511
    const int row  = blockIdx.x * 4 + (t >> 7);
    const int ct   = t & 127;
    const unsigned lane = t & 31;
    const int wid  = t >> 5;

    float4 v = ((const float4*)x)[(size_t)row * 128 + ct];
    v.x -= 0.5f; v.y -= 0.5f; v.z -= 0.5f; v.w -= 0.5f;
    v.y += v.x; v.z += v.y; v.w += v.z;
    const float tot = v.w;

    float s = tot;
    #pragma unroll
    for (int off = 1; off < 32; off <<= 1) {
        float nb = __shfl_up_sync(0xffffffffu, s, off);
        if (lane >= off) s += nb;
    }

    __shared__ float wtot[16];
    if (lane == 31) wtot[wid] = s;
    __syncthreads();

    float woff = 0.f;
    const int g0 = wid & ~3;
    #pragma unroll
    for (int j = 0; j < 3; j++)
        if (g0 + j < wid) woff += wtot[g0 + j];

    const float base = (s - tot) + woff;
    v.x += base; v.y += base; v.z += base; v.w += base;
    ((float4*)g_sat)[(size_t)row * 128 + ct] = v;
}

// ---------------------------------------------------------------------------
// Kernel B1: per-(img, chunk, col) partial column sums.
// ---------------------------------------------------------------------------
__global__ void col_chunksum_kernel() {
    const int t = blockIdx.x * blockDim.x + threadIdx.x;
    const int col   = t & (SW - 1);
    const int chunk = (t >> 9) & (NCHUNK - 1);
    const int img   = t >> 12;
    const float* p = g_sat + (size_t)img * SW * SW + (size_t)chunk * CROWS * SW + col;
    float sum = 0.f;
    #pragma unroll
    for (int y = 0; y < CROWS; y++) sum += p[(size_t)y * SW];
    g_csum[t] = sum;
}

// ---------------------------------------------------------------------------
// Kernel B2: chunk-prefix offset + in-place 64-row scan.
// ---------------------------------------------------------------------------
__global__ void col_scan_kernel() {
    const int t = blockIdx.x * blockDim.x + threadIdx.x;
    const int col   = t & (SW - 1);
    const int chunk = (t >> 9) & (NCHUNK - 1);
    const int img   = t >> 12;

    float off = 0.f;
    const int cbase = (img * NCHUNK) * SW + col;
    #pragma unroll
    for (int c = 0; c < NCHUNK - 1; c++)
        if (c < chunk) off += g_csum[cbase + c * SW];

    float* p = g_sat + (size_t)img * SW * SW + (size_t)chunk * CROWS * SW + col;
    float run = off;
    #pragma unroll
    for (int y = 0; y < CROWS; y++) {
        run += p[(size_t)y * SW];
        p[(size_t)y * SW] = run;
    }
}

// ---------------------------------------------------------------------------
// Kernel C: tiled gather, offset-table addressing, interior fast path.
// ---------------------------------------------------------------------------
__global__ __launch_bounds__(256) void gather_kernel(
    const float* __restrict__ bm,
    const float* __restrict__ kp,
    const float* __restrict__ kn,
    float* __restrict__ out)
{
    __shared__ float sm[SMH * SMW];          // 35.3 KB
    __shared__ float cpos[RADIUS], cneg[RADIUS];
    __shared__ int4  soff[RADIUS];

    const int tid = threadIdx.x;
    if (tid < RADIUS) {
        const int cidx = tid * TABLE * TABLE + KMAX * TABLE + KMAX;
        const float p = kp[cidx];
        const float q = kn[cidx];
        cpos[tid] = (tid == 0) ? 0.5f * (p + q) : p;
        cneg[tid] = (tid == 0) ? 0.5f * (p + q) : q;
        const int k = k_of(tid);
        soff[tid] = make_int4( k * SMW + k,
                              -(k + 1) * SMW + k,
                               k * SMW - (k + 1),
                              -(k + 1) * SMW - (k + 1));
    }

    const int img = blockIdx.z;
    const int gy0 = blockIdx.y * TY - HALO;
    const int gx0 = blockIdx.x * TX - HALO;
    const float* sat = g_sat + (size_t)img * SW * SW;

    // Fill extended SAT tile: below-range -> 0, above-range -> clamped.
    for (int i = tid; i < SMH * SMW; i += 256) {
        const int r  = i / SMW;
        const int c  = i - r * SMW;
        const int gy = gy0 + r;
        const int gx = gx0 + c;
        float v = 0.f;
        if (gy >= 0 && gx >= 0)
            v = sat[(size_t)min(gy, IMG_H - 1) * SW + min(gx, IMG_W - 1)];
        sm[r * SMW + c] = v;
    }
    __syncthreads();

    const bool interior = (blockIdx.x >= 1) & (blockIdx.x <= 6) &
                          (blockIdx.y >= 2) & (blockIdx.y <= 29);

    const int lx    = tid & (TX - 1);
    const int ly4   = tid >> 6;
    const int x     = blockIdx.x * TX + lx;
    const int ybase = blockIdx.y * TY + ly4 * 4;
    const int cx    = x - gx0;

    #pragma unroll
    for (int j = 0; j < 4; j++) {
        const int y    = ybase + j;
        const int pix  = (img << 18) | (y << 9) | x;
        const float b  = bm[pix];
        const int  cy  = y - gy0;
        const int  base = cy * SMW + cx;

        const float a = fabsf(b);
        int   i0 = (int)a;
        const float f = a - (float)i0;
        const bool pos = (b >= 0.f);

        float w0 = 1.f - f, w1 = f;
        int i1 = i0 + 1;
        if (i0 >= RADIUS) { i0 = 0; w0 = 0.f; }
        if (i1 >= RADIUS) { i1 = 0; w1 = 0.f; }

        const int4 o0 = soff[i0];
        const int4 o1 = soff[i1];
        const float c0 = pos ? cpos[i0] : cneg[i0];
        const float c1 = pos ? cpos[i1] : cneg[i1];

        const float S0 = sm[base + o0.x] - sm[base + o0.y]
                       - sm[base + o0.z] + sm[base + o0.w];
        const float S1 = sm[base + o1.x] - sm[base + o1.y]
                       - sm[base + o1.z] + sm[base + o1.w];

        float acc = w0 * c0 * S0 + w1 * c1 * S1;
        if (interior) {
            acc += 0.5f * (w0 + w1);           // c*cnt == 1 per level
        } else {
            const int k0 = k_of(i0);
            const int k1 = k_of(i1);
            const float cnt0 = (float)((min(y + k0, IMG_H - 1) - max(y - k0, 0) + 1)
                                     * (min(x + k0, IMG_W - 1) - max(x - k0, 0) + 1));
            const float cnt1 = (float)((min(y + k1, IMG_H - 1) - max(y - k1, 0) + 1)
                                     * (min(x + k1, IMG_W - 1) - max(x - k1, 0) + 1));
            acc += 0.5f * (w0 * c0 * cnt0 + w1 * c1 * cnt1);
        }
        out[pix] = acc;
    }
}

// ---------------------------------------------------------------------------
// kernel_launch
// ---------------------------------------------------------------------------
extern "C" void kernel_launch(void* const* d_in, const int* in_sizes, int n_in,
                              void* d_out, int out_size)
{
    const float* bm = (const float*)d_in[0];
    const float* x  = (const float*)d_in[1];
    const float* kp = (const float*)d_in[2];
    const float* kn = (const float*)d_in[3];
    float* out = (float*)d_out;

    row_scan_kernel<<<NIMG * IMG_H / 4, 512>>>(x);
    const int ncol = NIMG * NCHUNK * SW;     // 98304
    col_chunksum_kernel<<<ncol / 256, 256>>>();
    col_scan_kernel<<<ncol / 256, 256>>>();

    dim3 ggrid(IMG_W / TX, IMG_H / TY, NIMG);  // 8 x 32 x 24
    gather_kernel<<<ggrid, 256>>>(bm, kp, kn, out);
}